// round 16
// baseline (speedup 1.0000x reference)
#include <cuda_runtime.h>
#include <cuda_bf16.h>
#include <cuda_fp16.h>
#include <math.h>
#include <stdint.h>

#define BB 4
#define NN 4096
#define CC 128

// fp16 q,k,v. q is pre-scaled by log2(e) so attention works in base-2 domain.
__device__ __half g_qf[BB * NN * CC];
__device__ __half g_kf[BB * NN * CC];
__device__ __half g_vf[BB * NN * CC];

// grid-barrier counters (reset to 0 by the last departing CTA each launch)
__device__ unsigned int g_arrive = 0;
__device__ unsigned int g_depart = 0;

// ---------------------------------------------------------------------------
// PTX helpers (compute_103-baseline features only)
// ---------------------------------------------------------------------------
__device__ __forceinline__ uint32_t smem_u32(const void* p) {
    uint32_t a;
    asm("{ .reg .u64 t; cvta.to.shared.u64 t, %1; cvt.u32.u64 %0, t; }"
        : "=r"(a) : "l"(p));
    return a;
}
__device__ __forceinline__ void ldsm4(uint32_t a, uint32_t r[4]) {
    asm volatile("ldmatrix.sync.aligned.m8n8.x4.shared.b16 {%0,%1,%2,%3}, [%4];"
        : "=r"(r[0]), "=r"(r[1]), "=r"(r[2]), "=r"(r[3]) : "r"(a));
}
__device__ __forceinline__ void ldsm4t(uint32_t a, uint32_t r[4]) {
    asm volatile("ldmatrix.sync.aligned.m8n8.x4.trans.shared.b16 {%0,%1,%2,%3}, [%4];"
        : "=r"(r[0]), "=r"(r[1]), "=r"(r[2]), "=r"(r[3]) : "r"(a));
}
__device__ __forceinline__ void ldsm2t(uint32_t a, uint32_t r[2]) {
    asm volatile("ldmatrix.sync.aligned.m8n8.x2.trans.shared.b16 {%0,%1}, [%2];"
        : "=r"(r[0]), "=r"(r[1]) : "r"(a));
}
__device__ __forceinline__ void mma_bf16(float c[4], const uint32_t a[4],
                                         uint32_t b0, uint32_t b1) {
    asm volatile(
        "mma.sync.aligned.m16n8k16.row.col.f32.bf16.bf16.f32 "
        "{%0,%1,%2,%3}, {%4,%5,%6,%7}, {%8,%9}, {%0,%1,%2,%3};"
        : "+f"(c[0]), "+f"(c[1]), "+f"(c[2]), "+f"(c[3])
        : "r"(a[0]), "r"(a[1]), "r"(a[2]), "r"(a[3]), "r"(b0), "r"(b1));
}
__device__ __forceinline__ void mma_f16(float c[4], const uint32_t a[4],
                                        uint32_t b0, uint32_t b1) {
    asm volatile(
        "mma.sync.aligned.m16n8k16.row.col.f32.f16.f16.f32 "
        "{%0,%1,%2,%3}, {%4,%5,%6,%7}, {%8,%9}, {%0,%1,%2,%3};"
        : "+f"(c[0]), "+f"(c[1]), "+f"(c[2]), "+f"(c[3])
        : "r"(a[0]), "r"(a[1]), "r"(a[2]), "r"(a[3]), "r"(b0), "r"(b1));
}
__device__ __forceinline__ void cpa16(uint32_t dst, const void* src) {
    asm volatile("cp.async.cg.shared.global [%0], [%1], 16;" :: "r"(dst), "l"(src));
}
#define CPA_COMMIT() asm volatile("cp.async.commit_group;" ::: "memory")
#define CPA_WAIT(n)  asm volatile("cp.async.wait_group %0;" :: "n"(n) : "memory")

__device__ __forceinline__ uint32_t packbf(__nv_bfloat16 a, __nv_bfloat16 b) {
    return (uint32_t)__bfloat16_as_ushort(a)
         | ((uint32_t)__bfloat16_as_ushort(b) << 16);
}
__device__ __forceinline__ uint32_t packh(__half a, __half b) {
    return (uint32_t)__half_as_ushort(a)
         | ((uint32_t)__half_as_ushort(b) << 16);
}
__device__ __forceinline__ float ex2(float x) {
    float y;
    asm("ex2.approx.ftz.f32 %0, %1;" : "=f"(y) : "f"(x));
    return y;
}
__device__ __forceinline__ uint32_t cvth2(float hi, float lo) {
    uint32_t r;
    asm("cvt.rn.f16x2.f32 %0, %1, %2;" : "=r"(r) : "f"(hi), "f"(lo));
    return r;
}
__device__ __forceinline__ uint32_t ex2h2(uint32_t a) {
    uint32_t r;
    asm("ex2.approx.f16x2 %0, %1;" : "=r"(r) : "r"(a));
    return r;
}

#define QSTR 272   // smem row stride (bytes): conflict-free ldmatrix
#define LOG2E 1.4426950408889634f

// ---------------------------------------------------------------------------
// Shared-memory union (104448 bytes total, 2 CTAs/SM):
//   proj phase:  XH[64r]=0..17408, XL=17408..34816, WH[128r]=34816..69632,
//                WL=69632..104448
//   attn phase:  QF=0..17408, K 2 stages=17408..52224, V 3 stages=52224..104448
// ---------------------------------------------------------------------------
#define PX_H  0
#define PX_L  17408
#define PW_H  34816
#define PW_L  69632

#define TSZ   17408
#define SM_QF 0
#define SM_K  17408
#define SM_V  (SM_K + 2 * TSZ)
#define ASM_TOTAL (SM_V + 3 * TSZ)   // 104448

// stage a 128x128 fp32 weight matrix (global) -> bf16 hi/lo smem, 128 threads
__device__ __forceinline__ void stage_w(const float* __restrict__ src,
                                        char* __restrict__ sm, int tid)
{
    const float4* sg = (const float4*)src;
    #pragma unroll
    for (int i = 0; i < 32; i++) {
        int i4 = tid + i * 128;              // 4096 float4
        int r = i4 >> 5, c = (i4 & 31) << 2;
        float4 v = sg[i4];
        uint32_t d = (uint32_t)(r * QSTR + c * 2);
        __nv_bfloat16 hx = __float2bfloat16(v.x);
        __nv_bfloat16 hy = __float2bfloat16(v.y);
        __nv_bfloat16 hz = __float2bfloat16(v.z);
        __nv_bfloat16 hw = __float2bfloat16(v.w);
        *(uint32_t*)(sm + PW_H + d)     = packbf(hx, hy);
        *(uint32_t*)(sm + PW_H + d + 4) = packbf(hz, hw);
        *(uint32_t*)(sm + PW_L + d) = packbf(
            __float2bfloat16(v.x - __bfloat162float(hx)),
            __float2bfloat16(v.y - __bfloat162float(hy)));
        *(uint32_t*)(sm + PW_L + d + 4) = packbf(
            __float2bfloat16(v.z - __bfloat162float(hz)),
            __float2bfloat16(v.w - __bfloat162float(hw)));
    }
}

// 64-row x-tile (global fp32) -> bf16 hi/lo smem, 128 threads
__device__ __forceinline__ void stage_x64(const float* __restrict__ src,
                                          char* __restrict__ sm, int tid)
{
    const float4* sg = (const float4*)src;
    #pragma unroll
    for (int i = 0; i < 16; i++) {
        int i4 = tid + i * 128;              // 2048 float4
        int r = i4 >> 5, c = (i4 & 31) << 2;
        float4 v = sg[i4];
        uint32_t d = (uint32_t)(r * QSTR + c * 2);
        __nv_bfloat16 hx = __float2bfloat16(v.x);
        __nv_bfloat16 hy = __float2bfloat16(v.y);
        __nv_bfloat16 hz = __float2bfloat16(v.z);
        __nv_bfloat16 hw = __float2bfloat16(v.w);
        *(uint32_t*)(sm + PX_H + d)     = packbf(hx, hy);
        *(uint32_t*)(sm + PX_H + d + 4) = packbf(hz, hw);
        *(uint32_t*)(sm + PX_L + d) = packbf(
            __float2bfloat16(v.x - __bfloat162float(hx)),
            __float2bfloat16(v.y - __bfloat162float(hy)));
        *(uint32_t*)(sm + PX_L + d + 4) = packbf(
            __float2bfloat16(v.z - __bfloat162float(hz)),
            __float2bfloat16(v.w - __bfloat162float(hw)));
    }
}

// one 64x128 projection GEMM (3-pass bf16 split) + GELU + fp16 store
__device__ __forceinline__ void proj64(
    uint32_t sb, const float* __restrict__ bias, float oscale,
    __half* __restrict__ of, int grow0, int lane,
    uint32_t a_lrow, uint32_t b_lrow)
{
    float acc[16][4];
    #pragma unroll
    for (int j = 0; j < 16; j++)
        #pragma unroll
        for (int q = 0; q < 4; q++) acc[j][q] = 0.0f;

    #pragma unroll
    for (int c = 0; c < 8; c++) {
        uint32_t ah[4], al[4];
        ldsm4(sb + PX_H + a_lrow + 32 * c, ah);
        ldsm4(sb + PX_L + a_lrow + 32 * c, al);
        #pragma unroll
        for (int jg = 0; jg < 8; jg++) {
            uint32_t bh[4], bl[4];
            uint32_t ba = sb + PW_H + (uint32_t)(jg * 16 * QSTR) + b_lrow + 32 * c;
            ldsm4(ba, bh);
            ldsm4(ba + (PW_L - PW_H), bl);
            mma_bf16(acc[2 * jg],     ah, bh[0], bh[1]);
            mma_bf16(acc[2 * jg],     ah, bl[0], bl[1]);
            mma_bf16(acc[2 * jg],     al, bh[0], bh[1]);
            mma_bf16(acc[2 * jg + 1], ah, bh[2], bh[3]);
            mma_bf16(acc[2 * jg + 1], ah, bl[2], bl[3]);
            mma_bf16(acc[2 * jg + 1], al, bh[2], bh[3]);
        }
    }

    int r0 = grow0 + (lane >> 2);
    int r1 = r0 + 8;
    int colb = (lane & 3) * 2;
    #pragma unroll
    for (int j = 0; j < 16; j++) {
        int col = 8 * j + colb;
        float2 bb = *(const float2*)(bias + col);
        float v00 = acc[j][0] + bb.x, v01 = acc[j][1] + bb.y;
        float v10 = acc[j][2] + bb.x, v11 = acc[j][3] + bb.y;
        float g00 = 0.5f * v00 * (1.0f + erff(v00 * 0.70710678f)) * oscale;
        float g01 = 0.5f * v01 * (1.0f + erff(v01 * 0.70710678f)) * oscale;
        float g10 = 0.5f * v10 * (1.0f + erff(v10 * 0.70710678f)) * oscale;
        float g11 = 0.5f * v11 * (1.0f + erff(v11 * 0.70710678f)) * oscale;
        *(uint32_t*)(of + (size_t)r0 * 128 + col) =
            packh(__float2half_rn(g00), __float2half_rn(g01));
        *(uint32_t*)(of + (size_t)r1 * 128 + col) =
            packh(__float2half_rn(g10), __float2half_rn(g11));
    }
}

// ---------------------------------------------------------------------------
// Fused kernel: per-CTA projection of its 64 rows (q,k,v) -> grid barrier ->
// flash attention (validated R12 state). 256 CTAs x 128 threads, 2 CTAs/SM;
// all CTAs resident in one wave, so the spin barrier cannot deadlock.
// ---------------------------------------------------------------------------
__global__ __launch_bounds__(128, 2) void fused_kernel(
    float* __restrict__ out,
    const float* __restrict__ x,
    const float* __restrict__ Wq,
    const float* __restrict__ Wk,
    const float* __restrict__ Wv,
    const float* __restrict__ bq,
    const float* __restrict__ bk,
    const float* __restrict__ bv)
{
    extern __shared__ char sm[];
    const uint32_t sb = smem_u32(sm);
    const int tid = threadIdx.x;
    const int w = tid >> 5;
    const int lane = tid & 31;

    const int bid = blockIdx.x;
    const int batch = bid >> 6;
    const size_t qoff = (size_t)bid * 64 * CC;
    const size_t kvoff = (size_t)batch * NN * CC;

    const int R = w * 16;
    const uint32_t q_lrow = (uint32_t)((R + (lane & 15)) * QSTR + ((lane >> 4) << 4));
    const uint32_t k_lrow = (uint32_t)(((lane & 7) + ((lane >> 4) << 3)) * QSTR
                                       + (((lane >> 3) & 1) << 4));
    const uint32_t v_lrow = (uint32_t)(((lane & 7) + (((lane >> 3) & 1) << 3)) * QSTR
                                       + ((lane >> 4) << 4));
    const uint32_t vs_lrow = (uint32_t)((lane & 15) * QSTR + 256);

    // =================== phase 1: project this CTA's 64 rows ===============
    {
        const int grow0 = bid * 64 + R;
        stage_x64(x + (size_t)bid * 64 * CC, sm, tid);

        stage_w(Wq, sm, tid);
        __syncthreads();
        proj64(sb, bq, LOG2E, g_qf, grow0, lane, q_lrow, k_lrow);
        __syncthreads();

        stage_w(Wk, sm, tid);
        __syncthreads();
        proj64(sb, bk, 1.0f, g_kf, grow0, lane, q_lrow, k_lrow);
        __syncthreads();

        stage_w(Wv, sm, tid);
        __syncthreads();
        proj64(sb, bv, 1.0f, g_vf, grow0, lane, q_lrow, k_lrow);
    }

    // =================== grid barrier (all 256 CTAs resident) ===============
    __threadfence();
    __syncthreads();
    if (tid == 0) {
        atomicAdd(&g_arrive, 1u);
        while (*(volatile unsigned int*)&g_arrive < 256u) {}
        unsigned int d = atomicAdd(&g_depart, 1u);
        if (d == 255u) {            // last departer resets for the next launch
            g_arrive = 0u;
            g_depart = 0u;
            __threadfence();
        }
    }
    __syncthreads();
    __threadfence();                // acquire: see all CTAs' q/k/v stores

    // =================== phase 2: flash attention ===========================
    #pragma unroll
    for (int i = 0; i < 8; i++) {
        int cid = tid + i * 128;
        int r = cid >> 4, c = cid & 15;
        uint32_t d = (uint32_t)(r * QSTR + c * 16);
        size_t g = (size_t)r * 128 + c * 8;
        cpa16(sb + SM_QF + d, g_qf + qoff + g);
        cpa16(sb + SM_K + d, g_kf + kvoff + g);
        cpa16(sb + SM_V + d, g_vf + kvoff + g);
    }
    CPA_COMMIT();
    #pragma unroll
    for (int i = 0; i < 8; i++) {
        int cid = tid + i * 128;
        int r = cid >> 4, c = cid & 15;
        uint32_t d = (uint32_t)(r * QSTR + c * 16);
        size_t g = (size_t)(r + 64) * 128 + c * 8;
        cpa16(sb + SM_K + TSZ + d, g_kf + kvoff + g);
        cpa16(sb + SM_V + TSZ + d, g_vf + kvoff + g);
    }
    CPA_COMMIT();

    // ones-column for the l-sum MMA in all 3 V stages (bytes 256..271/row)
    if (tid < 64) {
        uint4 ones = make_uint4(0x3C00u, 0u, 0u, 0u);
        #pragma unroll
        for (int s = 0; s < 3; s++)
            *(uint4*)(sm + SM_V + s * TSZ + tid * QSTR + 256) = ones;
    }

    float O[16][4];
    #pragma unroll
    for (int j = 0; j < 16; j++)
        #pragma unroll
        for (int q = 0; q < 4; q++) O[j][q] = 0.0f;
    float Ol[4] = {0.0f, 0.0f, 0.0f, 0.0f};
    float m0 = -1e30f, m1 = -1e30f;

    CPA_WAIT(1);      // group 0 (Q,K0,V0) complete
    __syncthreads();

    // hoist Q fragments (reused across all 64 key tiles)
    uint32_t qf[8][4];
    #pragma unroll
    for (int c = 0; c < 8; c++)
        ldsm4(sb + SM_QF + q_lrow + 32 * c, qf[c]);

    for (int t = 0; t < NN / 64; t++) {
        const uint32_t kb = sb + SM_K + (uint32_t)((t & 1) * TSZ);

        // ---- S = Q K^T, single fp16 pass (logits in log2 units)
        float S[8][4];
        #pragma unroll
        for (int j = 0; j < 8; j++)
            #pragma unroll
            for (int q = 0; q < 4; q++) S[j][q] = 0.0f;

        #pragma unroll
        for (int c = 0; c < 8; c++) {
            #pragma unroll
            for (int jg = 0; jg < 4; jg++) {
                uint32_t bh[4];
                ldsm4(kb + (uint32_t)(jg * 16 * QSTR) + k_lrow + 32 * c, bh);
                mma_f16(S[2 * jg],     qf[c], bh[0], bh[1]);
                mma_f16(S[2 * jg + 1], qf[c], bh[2], bh[3]);
            }
        }

        // ---- shuffle-free overflow check: per-lane max vs m + 14.
        float mx0 = S[0][0], mx1 = S[0][2];
        #pragma unroll
        for (int j = 0; j < 8; j++) {
            mx0 = fmaxf(mx0, fmaxf(S[j][0], S[j][1]));
            mx1 = fmaxf(mx1, fmaxf(S[j][2], S[j][3]));
        }
        if (__any_sync(0xffffffffu,
                       (mx0 > m0 + 14.0f) || (mx1 > m1 + 14.0f))) {
            #pragma unroll
            for (int off = 1; off <= 2; off <<= 1) {
                mx0 = fmaxf(mx0, __shfl_xor_sync(0xffffffffu, mx0, off));
                mx1 = fmaxf(mx1, __shfl_xor_sync(0xffffffffu, mx1, off));
            }
            float mn0 = fmaxf(m0, mx0), mn1 = fmaxf(m1, mx1);
            float cr0 = ex2(m0 - mn0), cr1 = ex2(m1 - mn1);
            #pragma unroll
            for (int j = 0; j < 16; j++) {
                O[j][0] *= cr0; O[j][1] *= cr0;
                O[j][2] *= cr1; O[j][3] *= cr1;
            }
            Ol[0] *= cr0; Ol[1] *= cr0;
            Ol[2] *= cr1; Ol[3] *= cr1;
            m0 = mn0; m1 = mn1;
        }

        // ---- P = exp2(S - m), computed directly into fp16x2 A-fragments
        uint32_t ph[4][4];
        #pragma unroll
        for (int c = 0; c < 4; c++) {
            #pragma unroll
            for (int half = 0; half < 2; half++) {
                const float* sv = S[2 * c + half];
                ph[c][2 * half + 0] = ex2h2(cvth2(sv[1] - m0, sv[0] - m0));
                ph[c][2 * half + 1] = ex2h2(cvth2(sv[3] - m1, sv[2] - m1));
            }
        }

        // ---- O += P V  and  Ol += P 1  (V stage t%3)
        uint32_t vbase = sb + SM_V + (uint32_t)((t % 3) * TSZ);
        #pragma unroll
        for (int c = 0; c < 4; c++) {
            #pragma unroll
            for (int jg = 0; jg < 8; jg++) {
                uint32_t vh[4];
                ldsm4t(vbase + (uint32_t)(16 * c * QSTR) + v_lrow + 32 * jg, vh);
                mma_f16(O[2 * jg],     ph[c], vh[0], vh[1]);
                mma_f16(O[2 * jg + 1], ph[c], vh[2], vh[3]);
            }
            uint32_t vo[2];
            ldsm2t(vbase + (uint32_t)(16 * c * QSTR) + vs_lrow, vo);
            mma_f16(Ol, ph[c], vo[0], vo[1]);
        }

        // ---- all warps finished reading K(t) and V(t); prefetch t+2
        __syncthreads();
        if (t + 2 < NN / 64) {
            size_t gkv = kvoff + (size_t)(t + 2) * 64 * 128;
            uint32_t kdst = sb + SM_K + (uint32_t)((t & 1) * TSZ);
            uint32_t vdst = sb + SM_V + (uint32_t)(((t + 2) % 3) * TSZ);
            #pragma unroll
            for (int i = 0; i < 8; i++) {
                int cid = tid + i * 128;
                int r = cid >> 4, c = cid & 15;
                uint32_t d = (uint32_t)(r * QSTR + c * 16);
                size_t g = gkv + (size_t)r * 128 + c * 8;
                cpa16(kdst + d, g_kf + g);
                cpa16(vdst + d, g_vf + g);
            }
            CPA_COMMIT();
            CPA_WAIT(1);   // group t+1 complete; t+2 still in flight
        } else {
            CPA_WAIT(0);
        }
    }

    // ---- epilogue: l lives in the ones-column accumulator of quad-lane 0
    {
        float l0 = __shfl_sync(0xffffffffu, Ol[0], lane & 28);
        float l1 = __shfl_sync(0xffffffffu, Ol[2], lane & 28);
        float inv0 = 1.0f / l0, inv1 = 1.0f / l1;
        size_t gr0 = (size_t)bid * 64 + R + (lane >> 2);
        size_t gr1 = gr0 + 8;
        int colb = (lane & 3) * 2;
        #pragma unroll
        for (int j = 0; j < 16; j++) {
            int col = 8 * j + colb;
            *(float2*)&out[gr0 * 128 + col] = make_float2(O[j][0] * inv0, O[j][1] * inv0);
            *(float2*)&out[gr1 * 128 + col] = make_float2(O[j][2] * inv1, O[j][3] * inv1);
        }
    }
}

// ---------------------------------------------------------------------------
extern "C" void kernel_launch(void* const* d_in, const int* in_sizes, int n_in,
                              void* d_out, int out_size)
{
    (void)in_sizes; (void)n_in; (void)out_size;
    const float* x  = (const float*)d_in[0];
    const float* Wq = (const float*)d_in[1];
    const float* bq = (const float*)d_in[2];
    const float* Wk = (const float*)d_in[3];
    const float* bk = (const float*)d_in[4];
    const float* Wv = (const float*)d_in[5];
    const float* bv = (const float*)d_in[6];
    float* out = (float*)d_out;

    cudaFuncSetAttribute(fused_kernel,
                         cudaFuncAttributeMaxDynamicSharedMemorySize, ASM_TOTAL);

    fused_kernel<<<BB * NN / 64, 128, ASM_TOTAL>>>(out, x, Wq, Wk, Wv,
                                                   bq, bk, bv);
}

// round 17
// speedup vs baseline: 1.0754x; 1.0754x over previous
#include <cuda_runtime.h>
#include <cuda_bf16.h>
#include <cuda_fp16.h>
#include <math.h>
#include <stdint.h>

#define BB 4
#define NN 4096
#define CC 128

// fp16 q,k,v. q is pre-scaled by log2(e) so attention works in base-2 domain.
__device__ __half g_qf[BB * NN * CC];
__device__ __half g_kf[BB * NN * CC];
__device__ __half g_vf[BB * NN * CC];

// ---------------------------------------------------------------------------
// PTX helpers (compute_103-baseline features only)
// ---------------------------------------------------------------------------
__device__ __forceinline__ uint32_t smem_u32(const void* p) {
    uint32_t a;
    asm("{ .reg .u64 t; cvta.to.shared.u64 t, %1; cvt.u32.u64 %0, t; }"
        : "=r"(a) : "l"(p));
    return a;
}
__device__ __forceinline__ void ldsm4(uint32_t a, uint32_t r[4]) {
    asm volatile("ldmatrix.sync.aligned.m8n8.x4.shared.b16 {%0,%1,%2,%3}, [%4];"
        : "=r"(r[0]), "=r"(r[1]), "=r"(r[2]), "=r"(r[3]) : "r"(a));
}
__device__ __forceinline__ void ldsm4t(uint32_t a, uint32_t r[4]) {
    asm volatile("ldmatrix.sync.aligned.m8n8.x4.trans.shared.b16 {%0,%1,%2,%3}, [%4];"
        : "=r"(r[0]), "=r"(r[1]), "=r"(r[2]), "=r"(r[3]) : "r"(a));
}
__device__ __forceinline__ void ldsm2t(uint32_t a, uint32_t r[2]) {
    asm volatile("ldmatrix.sync.aligned.m8n8.x2.trans.shared.b16 {%0,%1}, [%2];"
        : "=r"(r[0]), "=r"(r[1]) : "r"(a));
}
__device__ __forceinline__ void mma_bf16(float c[4], const uint32_t a[4],
                                         uint32_t b0, uint32_t b1) {
    asm volatile(
        "mma.sync.aligned.m16n8k16.row.col.f32.bf16.bf16.f32 "
        "{%0,%1,%2,%3}, {%4,%5,%6,%7}, {%8,%9}, {%0,%1,%2,%3};"
        : "+f"(c[0]), "+f"(c[1]), "+f"(c[2]), "+f"(c[3])
        : "r"(a[0]), "r"(a[1]), "r"(a[2]), "r"(a[3]), "r"(b0), "r"(b1));
}
__device__ __forceinline__ void mma_f16(float c[4], const uint32_t a[4],
                                        uint32_t b0, uint32_t b1) {
    asm volatile(
        "mma.sync.aligned.m16n8k16.row.col.f32.f16.f16.f32 "
        "{%0,%1,%2,%3}, {%4,%5,%6,%7}, {%8,%9}, {%0,%1,%2,%3};"
        : "+f"(c[0]), "+f"(c[1]), "+f"(c[2]), "+f"(c[3])
        : "r"(a[0]), "r"(a[1]), "r"(a[2]), "r"(a[3]), "r"(b0), "r"(b1));
}
__device__ __forceinline__ void cpa16(uint32_t dst, const void* src) {
    asm volatile("cp.async.cg.shared.global [%0], [%1], 16;" :: "r"(dst), "l"(src));
}
#define CPA_COMMIT() asm volatile("cp.async.commit_group;" ::: "memory")
#define CPA_WAIT(n)  asm volatile("cp.async.wait_group %0;" :: "n"(n) : "memory")

__device__ __forceinline__ uint32_t packbf(__nv_bfloat16 a, __nv_bfloat16 b) {
    return (uint32_t)__bfloat16_as_ushort(a)
         | ((uint32_t)__bfloat16_as_ushort(b) << 16);
}
__device__ __forceinline__ uint32_t packh(__half a, __half b) {
    return (uint32_t)__half_as_ushort(a)
         | ((uint32_t)__half_as_ushort(b) << 16);
}
__device__ __forceinline__ float ex2(float x) {
    float y;
    asm("ex2.approx.ftz.f32 %0, %1;" : "=f"(y) : "f"(x));
    return y;
}
__device__ __forceinline__ uint32_t cvth2(float hi, float lo) {
    uint32_t r;
    asm("cvt.rn.f16x2.f32 %0, %1, %2;" : "=r"(r) : "f"(hi), "f"(lo));
    return r;
}
__device__ __forceinline__ uint32_t ex2h2(uint32_t a) {
    uint32_t r;
    asm("ex2.approx.f16x2 %0, %1;" : "=r"(r) : "r"(a));
    return r;
}

// fast tanh-form GELU: 0.5 v (1 + tanh(0.79788456(v + 0.044715 v^3)))
//                    = v * t / (t + 1),  t = 2^(2*log2e*0.79788456*(v+0.044715 v^3))
__device__ __forceinline__ float gelu_fast(float v) {
    float v2 = v * v;
    float y = v * (2.302118f + 0.102948135f * v2);   // 2*log2e*0.79788456*(1, 0.044715)
    float t = ex2(y);
    return v * (t * __fdividef(1.0f, t + 1.0f));
}

#define QSTR 272   // smem row stride (bytes): conflict-free ldmatrix
#define LOG2E 1.4426950408889634f

// ---------------------------------------------------------------------------
// Fused tensor-core projection: q,k,v = fp16(gelu(xW^T+b)); q scaled by
// log2(e). Internal compute: 3-pass bf16 split. (R12 structure; fast GELU.)
// ---------------------------------------------------------------------------
#define PSM_XH 0
#define PSM_XL 34816
#define PSM_WH 69632
#define PSM_WL 104448
#define PSM_B  139264
#define PSM_TOTAL (PSM_B + 1536)

__device__ __forceinline__ void proj_compute(
    uint32_t sb, const float* bias_s, float oscale,
    __half* __restrict__ of,
    int row0, int lane, uint32_t a_lrow, uint32_t b_lrow)
{
    float acc[16][4];
    #pragma unroll
    for (int j = 0; j < 16; j++)
        #pragma unroll
        for (int q = 0; q < 4; q++) acc[j][q] = 0.0f;

    #pragma unroll
    for (int c = 0; c < 8; c++) {
        uint32_t ah[4], al[4];
        ldsm4(sb + PSM_XH + a_lrow + 32 * c, ah);
        ldsm4(sb + PSM_XL + a_lrow + 32 * c, al);
        #pragma unroll
        for (int jg = 0; jg < 8; jg++) {
            uint32_t bh[4], bl[4];
            uint32_t ba = sb + PSM_WH + (uint32_t)(jg * 16 * QSTR) + b_lrow + 32 * c;
            ldsm4(ba, bh);
            ldsm4(ba + (PSM_WL - PSM_WH), bl);
            mma_bf16(acc[2 * jg],     ah, bh[0], bh[1]);
            mma_bf16(acc[2 * jg],     ah, bl[0], bl[1]);
            mma_bf16(acc[2 * jg],     al, bh[0], bh[1]);
            mma_bf16(acc[2 * jg + 1], ah, bh[2], bh[3]);
            mma_bf16(acc[2 * jg + 1], ah, bl[2], bl[3]);
            mma_bf16(acc[2 * jg + 1], al, bh[2], bh[3]);
        }
    }

    int r0 = row0 + (lane >> 2);
    int r1 = r0 + 8;
    int colb = (lane & 3) * 2;
    #pragma unroll
    for (int j = 0; j < 16; j++) {
        int col = 8 * j + colb;
        float b0 = bias_s[col], b1 = bias_s[col + 1];
        float g00 = gelu_fast(acc[j][0] + b0) * oscale;
        float g01 = gelu_fast(acc[j][1] + b1) * oscale;
        float g10 = gelu_fast(acc[j][2] + b0) * oscale;
        float g11 = gelu_fast(acc[j][3] + b1) * oscale;
        *(uint32_t*)(of + (size_t)r0 * 128 + col) =
            packh(__float2half_rn(g00), __float2half_rn(g01));
        *(uint32_t*)(of + (size_t)r1 * 128 + col) =
            packh(__float2half_rn(g10), __float2half_rn(g11));
    }
}

__device__ __forceinline__ void stage_split(const float* __restrict__ src,
                                            char* __restrict__ smh,
                                            char* __restrict__ sml, int tid)
{
    const float4* sg = (const float4*)src;
    #pragma unroll
    for (int i = 0; i < 16; i++) {
        int i4 = tid + i * 256;
        int r = i4 >> 5, c = (i4 & 31) << 2;
        float4 v = sg[i4];
        uint32_t d = (uint32_t)(r * QSTR + c * 2);
        __nv_bfloat16 hx = __float2bfloat16(v.x);
        __nv_bfloat16 hy = __float2bfloat16(v.y);
        __nv_bfloat16 hz = __float2bfloat16(v.z);
        __nv_bfloat16 hw = __float2bfloat16(v.w);
        *(uint32_t*)(smh + d)     = packbf(hx, hy);
        *(uint32_t*)(smh + d + 4) = packbf(hz, hw);
        *(uint32_t*)(sml + d) = packbf(
            __float2bfloat16(v.x - __bfloat162float(hx)),
            __float2bfloat16(v.y - __bfloat162float(hy)));
        *(uint32_t*)(sml + d + 4) = packbf(
            __float2bfloat16(v.z - __bfloat162float(hz)),
            __float2bfloat16(v.w - __bfloat162float(hw)));
    }
}

__global__ __launch_bounds__(256, 1) void proj_mma_kernel(
    const float* __restrict__ x,
    const float* __restrict__ Wq,
    const float* __restrict__ Wk,
    const float* __restrict__ Wv,
    const float* __restrict__ bq,
    const float* __restrict__ bk,
    const float* __restrict__ bv)
{
    extern __shared__ char sm[];
    const uint32_t sb = smem_u32(sm);
    const int tid = threadIdx.x;
    const int w = tid >> 5;
    const int lane = tid & 31;
    const int row0 = blockIdx.x * 128;

    stage_split(x + (size_t)row0 * 128, sm + PSM_XH, sm + PSM_XL, tid);
    {
        float* bias_s = (float*)(sm + PSM_B);
        if (tid < 128)      bias_s[tid] = bq[tid];
        else if (tid < 256) bias_s[tid] = bk[tid - 128];
        if (tid < 128)      bias_s[256 + tid] = bv[tid];
    }

    const int R = w * 16;
    const uint32_t a_lrow = (uint32_t)((R + (lane & 15)) * QSTR + ((lane >> 4) << 4));
    const uint32_t b_lrow = (uint32_t)(((lane & 7) + ((lane >> 4) << 3)) * QSTR
                                       + (((lane >> 3) & 1) << 4));
    const float* bias_s = (const float*)(sm + PSM_B);

    stage_split(Wq, sm + PSM_WH, sm + PSM_WL, tid);
    __syncthreads();
    proj_compute(sb, bias_s, LOG2E, g_qf, row0 + R, lane, a_lrow, b_lrow);
    __syncthreads();

    stage_split(Wk, sm + PSM_WH, sm + PSM_WL, tid);
    __syncthreads();
    proj_compute(sb, bias_s + 128, 1.0f, g_kf, row0 + R, lane, a_lrow, b_lrow);
    __syncthreads();

    stage_split(Wv, sm + PSM_WH, sm + PSM_WL, tid);
    __syncthreads();
    proj_compute(sb, bias_s + 256, 1.0f, g_vf, row0 + R, lane, a_lrow, b_lrow);
}

// ---------------------------------------------------------------------------
// Flash attention (validated R12 state): lazy rescale with shuffle-free
// common-path check. K double-buffered, V triple-buffered, 2-tile lookahead.
// 256 CTAs x 128 threads, 2 CTAs/SM.
// ---------------------------------------------------------------------------
#define TSZ   17408             // one 64-row tile (64*QSTR)
#define SM_QF 0
#define SM_K  17408             // 2 stages
#define SM_V  (SM_K + 2 * TSZ)  // 3 stages
#define ASM_TOTAL (SM_V + 3 * TSZ)   // 104448

__global__ __launch_bounds__(128, 2) void attn_mma_kernel(float* __restrict__ out)
{
    extern __shared__ char sm[];
    const uint32_t sb = smem_u32(sm);
    const int tid = threadIdx.x;
    const int w = tid >> 5;
    const int lane = tid & 31;

    const int bid = blockIdx.x;
    const int batch = bid >> 6;
    const size_t qoff = (size_t)bid * 64 * CC;
    const size_t kvoff = (size_t)batch * NN * CC;

    // ---- group 0: Q + K0 + V0; group 1: K1 + V1
    #pragma unroll
    for (int i = 0; i < 8; i++) {
        int cid = tid + i * 128;
        int r = cid >> 4, c = cid & 15;
        uint32_t d = (uint32_t)(r * QSTR + c * 16);
        size_t g = (size_t)r * 128 + c * 8;
        cpa16(sb + SM_QF + d, g_qf + qoff + g);
        cpa16(sb + SM_K + d, g_kf + kvoff + g);
        cpa16(sb + SM_V + d, g_vf + kvoff + g);
    }
    CPA_COMMIT();
    #pragma unroll
    for (int i = 0; i < 8; i++) {
        int cid = tid + i * 128;
        int r = cid >> 4, c = cid & 15;
        uint32_t d = (uint32_t)(r * QSTR + c * 16);
        size_t g = (size_t)(r + 64) * 128 + c * 8;
        cpa16(sb + SM_K + TSZ + d, g_kf + kvoff + g);
        cpa16(sb + SM_V + TSZ + d, g_vf + kvoff + g);
    }
    CPA_COMMIT();

    // ones-column for the l-sum MMA in all 3 V stages (bytes 256..271/row)
    if (tid < 64) {
        uint4 ones = make_uint4(0x3C00u, 0u, 0u, 0u);
        #pragma unroll
        for (int s = 0; s < 3; s++)
            *(uint4*)(sm + SM_V + s * TSZ + tid * QSTR + 256) = ones;
    }

    float O[16][4];
    #pragma unroll
    for (int j = 0; j < 16; j++)
        #pragma unroll
        for (int q = 0; q < 4; q++) O[j][q] = 0.0f;
    float Ol[4] = {0.0f, 0.0f, 0.0f, 0.0f};
    float m0 = -1e30f, m1 = -1e30f;

    const int R = w * 16;
    const uint32_t q_lrow = (uint32_t)((R + (lane & 15)) * QSTR + ((lane >> 4) << 4));
    const uint32_t k_lrow = (uint32_t)(((lane & 7) + ((lane >> 4) << 3)) * QSTR
                                       + (((lane >> 3) & 1) << 4));
    const uint32_t v_lrow = (uint32_t)(((lane & 7) + (((lane >> 3) & 1) << 3)) * QSTR
                                       + ((lane >> 4) << 4));
    const uint32_t vs_lrow = (uint32_t)((lane & 15) * QSTR + 256);

    CPA_WAIT(1);      // group 0 (Q,K0,V0) complete
    __syncthreads();

    // hoist Q fragments (reused across all 64 key tiles)
    uint32_t qf[8][4];
    #pragma unroll
    for (int c = 0; c < 8; c++)
        ldsm4(sb + SM_QF + q_lrow + 32 * c, qf[c]);

    for (int t = 0; t < NN / 64; t++) {
        const uint32_t kb = sb + SM_K + (uint32_t)((t & 1) * TSZ);

        // ---- S = Q K^T, single fp16 pass (logits in log2 units)
        float S[8][4];
        #pragma unroll
        for (int j = 0; j < 8; j++)
            #pragma unroll
            for (int q = 0; q < 4; q++) S[j][q] = 0.0f;

        #pragma unroll
        for (int c = 0; c < 8; c++) {
            #pragma unroll
            for (int jg = 0; jg < 4; jg++) {
                uint32_t bh[4];
                ldsm4(kb + (uint32_t)(jg * 16 * QSTR) + k_lrow + 32 * c, bh);
                mma_f16(S[2 * jg],     qf[c], bh[0], bh[1]);
                mma_f16(S[2 * jg + 1], qf[c], bh[2], bh[3]);
            }
        }

        // ---- shuffle-free overflow check: per-lane max vs m + 14.
        //      P = 2^(S-m) <= 2^14 stays fp16-safe without rescale.
        float mx0 = S[0][0], mx1 = S[0][2];
        #pragma unroll
        for (int j = 0; j < 8; j++) {
            mx0 = fmaxf(mx0, fmaxf(S[j][0], S[j][1]));
            mx1 = fmaxf(mx1, fmaxf(S[j][2], S[j][3]));
        }
        if (__any_sync(0xffffffffu,
                       (mx0 > m0 + 14.0f) || (mx1 > m1 + 14.0f))) {
            // rare path: true quad row-max, rescale O/Ol, bump m
            #pragma unroll
            for (int off = 1; off <= 2; off <<= 1) {
                mx0 = fmaxf(mx0, __shfl_xor_sync(0xffffffffu, mx0, off));
                mx1 = fmaxf(mx1, __shfl_xor_sync(0xffffffffu, mx1, off));
            }
            float mn0 = fmaxf(m0, mx0), mn1 = fmaxf(m1, mx1);
            float cr0 = ex2(m0 - mn0), cr1 = ex2(m1 - mn1);
            #pragma unroll
            for (int j = 0; j < 16; j++) {
                O[j][0] *= cr0; O[j][1] *= cr0;
                O[j][2] *= cr1; O[j][3] *= cr1;
            }
            Ol[0] *= cr0; Ol[1] *= cr0;
            Ol[2] *= cr1; Ol[3] *= cr1;
            m0 = mn0; m1 = mn1;
        }

        // ---- P = exp2(S - m), computed directly into fp16x2 A-fragments
        uint32_t ph[4][4];
        #pragma unroll
        for (int c = 0; c < 4; c++) {
            #pragma unroll
            for (int half = 0; half < 2; half++) {
                const float* sv = S[2 * c + half];
                ph[c][2 * half + 0] = ex2h2(cvth2(sv[1] - m0, sv[0] - m0));
                ph[c][2 * half + 1] = ex2h2(cvth2(sv[3] - m1, sv[2] - m1));
            }
        }

        // ---- O += P V  and  Ol += P 1  (V stage t%3)
        uint32_t vbase = sb + SM_V + (uint32_t)((t % 3) * TSZ);
        #pragma unroll
        for (int c = 0; c < 4; c++) {
            #pragma unroll
            for (int jg = 0; jg < 8; jg++) {
                uint32_t vh[4];
                ldsm4t(vbase + (uint32_t)(16 * c * QSTR) + v_lrow + 32 * jg, vh);
                mma_f16(O[2 * jg],     ph[c], vh[0], vh[1]);
                mma_f16(O[2 * jg + 1], ph[c], vh[2], vh[3]);
            }
            uint32_t vo[2];
            ldsm2t(vbase + (uint32_t)(16 * c * QSTR) + vs_lrow, vo);
            mma_f16(Ol, ph[c], vo[0], vo[1]);
        }

        // ---- all warps finished reading K(t) and V(t); prefetch t+2
        __syncthreads();
        if (t + 2 < NN / 64) {
            size_t gkv = kvoff + (size_t)(t + 2) * 64 * 128;
            uint32_t kdst = sb + SM_K + (uint32_t)((t & 1) * TSZ);
            uint32_t vdst = sb + SM_V + (uint32_t)(((t + 2) % 3) * TSZ);
            #pragma unroll
            for (int i = 0; i < 8; i++) {
                int cid = tid + i * 128;
                int r = cid >> 4, c = cid & 15;
                uint32_t d = (uint32_t)(r * QSTR + c * 16);
                size_t g = gkv + (size_t)r * 128 + c * 8;
                cpa16(kdst + d, g_kf + g);
                cpa16(vdst + d, g_vf + g);
            }
            CPA_COMMIT();
            CPA_WAIT(1);   // group t+1 complete; t+2 still in flight
        } else {
            CPA_WAIT(0);
        }
    }

    // ---- epilogue: l lives in the ones-column accumulator of quad-lane 0
    {
        float l0 = __shfl_sync(0xffffffffu, Ol[0], lane & 28);
        float l1 = __shfl_sync(0xffffffffu, Ol[2], lane & 28);
        float inv0 = 1.0f / l0, inv1 = 1.0f / l1;
        size_t gr0 = (size_t)bid * 64 + R + (lane >> 2);
        size_t gr1 = gr0 + 8;
        int colb = (lane & 3) * 2;
        #pragma unroll
        for (int j = 0; j < 16; j++) {
            int col = 8 * j + colb;
            *(float2*)&out[gr0 * 128 + col] = make_float2(O[j][0] * inv0, O[j][1] * inv0);
            *(float2*)&out[gr1 * 128 + col] = make_float2(O[j][2] * inv1, O[j][3] * inv1);
        }
    }
}

// ---------------------------------------------------------------------------
extern "C" void kernel_launch(void* const* d_in, const int* in_sizes, int n_in,
                              void* d_out, int out_size)
{
    (void)in_sizes; (void)n_in; (void)out_size;
    const float* x  = (const float*)d_in[0];
    const float* Wq = (const float*)d_in[1];
    const float* bq = (const float*)d_in[2];
    const float* Wk = (const float*)d_in[3];
    const float* bk = (const float*)d_in[4];
    const float* Wv = (const float*)d_in[5];
    const float* bv = (const float*)d_in[6];
    float* out = (float*)d_out;

    cudaFuncSetAttribute(proj_mma_kernel,
                         cudaFuncAttributeMaxDynamicSharedMemorySize, PSM_TOTAL);
    cudaFuncSetAttribute(attn_mma_kernel,
                         cudaFuncAttributeMaxDynamicSharedMemorySize, ASM_TOTAL);

    proj_mma_kernel<<<BB * NN / 128, 256, PSM_TOTAL>>>(x, Wq, Wk, Wv, bq, bk, bv);
    attn_mma_kernel<<<BB * NN / 64, 128, ASM_TOTAL>>>(out);
}